// round 4
// baseline (speedup 1.0000x reference)
#include <cuda_runtime.h>
#include <cuda_bf16.h>
#include <cstdint>

// Problem constants (fixed by the reference):
//   x: [4096, 200] integer tokens -> 819200 tokens (dtype int32 OR int64 — detected)
//   W: [128, 100000] fp32 (row-major: W[e*VOCAB + v])
//   b: [128] fp32
//   out[t*128 + e] = W[e*VOCAB + x[t]] + b[e]
#define VOCAB 100000
#define EMBED 128
#define NTOK  819200

// Scratch (static __device__ globals — no allocation in kernel_launch):
__device__ float g_Wt[(size_t)VOCAB * EMBED];  // 51.2 MB: bias-fused W^T
__device__ int   g_idx[NTOK];                  // 3.3 MB: normalized int32 indices
__device__ int   g_is64;                       // dtype flag

// ---------------------------------------------------------------------------
// Kernel 0a: detect index dtype. Sample odd int32 slots 1..63 (in-bounds for
// both interpretations: 64 int32 = first 32 int64 values). For int64 data
// with token values < 100000, all high words are 0. For int32 random tokens,
// P(all 32 sampled == 0) ~ 1e-160.
// ---------------------------------------------------------------------------
__global__ void detect_kernel(const int* __restrict__ xraw) {
    int v = xraw[2 * threadIdx.x + 1];
    unsigned nz = __ballot_sync(0xffffffffu, v != 0);
    if (threadIdx.x == 0) g_is64 = (nz == 0u) ? 1 : 0;
}

// ---------------------------------------------------------------------------
// Kernel 0b: normalize indices to int32 and clamp (crash-proofing: a bad
// index becomes a wrong value, not an illegal access).
// ---------------------------------------------------------------------------
__global__ void convert_kernel(const int* __restrict__ xraw) {
    const int t = blockIdx.x * blockDim.x + threadIdx.x;
    if (t >= NTOK) return;
    int idx = g_is64 ? xraw[2 * t]   // low word of little-endian int64
                     : xraw[t];
    idx = min(max(idx, 0), VOCAB - 1);
    g_idx[t] = idx;
}

// ---------------------------------------------------------------------------
// Kernel 1: tiled transpose with fused bias.
//   g_Wt[v*128 + e] = W[e*VOCAB + v] + b[e]
// VOCAB = 32*3125, EMBED = 32*4 exactly: no bounds checks.
// Block (32, 8), grid (3125, 4). Coalesced on both sides via smem tile.
// ---------------------------------------------------------------------------
__global__ void transpose_bias_kernel(const float* __restrict__ W,
                                      const float* __restrict__ b) {
    __shared__ float tile[32][33];   // +1 pad: conflict-free transpose

    const int v0 = blockIdx.x * 32;
    const int e0 = blockIdx.y * 32;
    const int tx = threadIdx.x;      // 0..31
    const int ty = threadIdx.y;      // 0..7

#pragma unroll
    for (int j = 0; j < 32; j += 8) {
        tile[ty + j][tx] =
            W[(size_t)(e0 + ty + j) * VOCAB + (size_t)(v0 + tx)];
    }
    __syncthreads();

    const float bias = b[e0 + tx];
#pragma unroll
    for (int j = 0; j < 32; j += 8) {
        g_Wt[(size_t)(v0 + ty + j) * EMBED + (size_t)(e0 + tx)] =
            tile[tx][ty + j] + bias;
    }
}

// ---------------------------------------------------------------------------
// Kernel 2: gather. One warp per token; each lane copies one float4
// (32 lanes * 16 B = 512 B = one embedding row). Fully coalesced 128 B
// transactions on both the g_Wt read (L2-resident) and the out write.
// ---------------------------------------------------------------------------
__global__ void gather_kernel(float4* __restrict__ out) {
    const unsigned gid = blockIdx.x * blockDim.x + threadIdx.x;
    const unsigned t = gid >> 5;         // token id (one warp per token)
    const unsigned c = gid & 31;         // float4 chunk within row

    const int idx = __ldg(&g_idx[t]);    // 4B broadcast across the warp

    const float4* __restrict__ src =
        reinterpret_cast<const float4*>(g_Wt) + (size_t)idx * 32 + c;
    out[(size_t)t * 32 + c] = *src;
}

// ---------------------------------------------------------------------------
// kernel_launch: metadata order x, W, b. Output fp32 [819200, 128].
// ---------------------------------------------------------------------------
extern "C" void kernel_launch(void* const* d_in, const int* in_sizes, int n_in,
                              void* d_out, int out_size) {
    const int*   xraw = (const int*)d_in[0];
    const float* W    = (const float*)d_in[1];
    const float* b    = (const float*)d_in[2];
    float4*      out  = (float4*)d_out;

    detect_kernel<<<1, 32>>>(xraw);
    convert_kernel<<<(NTOK + 255) / 256, 256>>>(xraw);

    dim3 tb_block(32, 8);
    dim3 tb_grid(VOCAB / 32, EMBED / 32);   // (3125, 4)
    transpose_bias_kernel<<<tb_grid, tb_block>>>(W, b);

    const unsigned total_threads = (unsigned)NTOK * 32u;  // 26,214,400
    const unsigned block = 256;
    const unsigned grid = total_threads / block;          // 102,400
    gather_kernel<<<grid, block>>>(out);
}

// round 5
// speedup vs baseline: 1.4942x; 1.4942x over previous
#include <cuda_runtime.h>
#include <cuda_bf16.h>
#include <cstdint>

// Problem constants:
//   x: [4096, 200] tokens -> 819200 (int32 or int64, runtime-detected)
//   W: [128, 100000] fp32 row-major;  b: [128] fp32
//   out[t*128 + e] = W[e*VOCAB + x[t]] + b[e]
#define VOCAB 100000
#define EMBED 128
#define NTOK  819200
#define TPW   8          // tokens per warp (MLP depth)

// Static scratch (no allocation in kernel_launch):
__device__ float g_Wt[(size_t)VOCAB * EMBED];  // 51.2 MB bias-fused W^T
__device__ int   g_is64;                       // index dtype flag

// ---------------------------------------------------------------------------
// Detect index dtype. Odd int32 slots 1..63 are in-bounds under either
// interpretation; for little-endian int64 tokens < 100000 all high words are
// zero. P(false positive with random int32 tokens) ~ 1e-160. Deterministic.
// ---------------------------------------------------------------------------
__global__ void detect_kernel(const int* __restrict__ xraw) {
    int v = xraw[2 * threadIdx.x + 1];
    unsigned nz = __ballot_sync(0xffffffffu, v != 0);
    if (threadIdx.x == 0) g_is64 = (nz == 0u) ? 1 : 0;
}

// ---------------------------------------------------------------------------
// Tiled transpose with fused bias: g_Wt[v*128 + e] = W[e*VOCAB + v] + b[e].
// VOCAB = 32*3125, EMBED = 32*4 exactly: no bounds checks.
// ---------------------------------------------------------------------------
__global__ void transpose_bias_kernel(const float* __restrict__ W,
                                      const float* __restrict__ b) {
    __shared__ float tile[32][33];

    const int v0 = blockIdx.x * 32;
    const int e0 = blockIdx.y * 32;
    const int tx = threadIdx.x;      // 0..31
    const int ty = threadIdx.y;      // 0..7

#pragma unroll
    for (int j = 0; j < 32; j += 8) {
        tile[ty + j][tx] =
            W[(size_t)(e0 + ty + j) * VOCAB + (size_t)(v0 + tx)];
    }
    __syncthreads();

    const float bias = b[e0 + tx];
#pragma unroll
    for (int j = 0; j < 32; j += 8) {
        g_Wt[(size_t)(v0 + ty + j) * EMBED + (size_t)(e0 + tx)] =
            tile[tx][ty + j] + bias;
    }
}

// ---------------------------------------------------------------------------
// Gather: one warp per 8 tokens.
//   - lanes 0..7 load 8 indices (coalesced), __shfl broadcasts
//   - 8 independent float4 row-loads issued back-to-back (MLP=8)
//   - 8 streaming stores (__stcs): evict-first so output traffic doesn't
//     thrash g_Wt out of L2.
// Index conversion (int64 low word vs int32) + clamp fused here.
// ---------------------------------------------------------------------------
__global__ void gather_kernel(const int* __restrict__ xraw,
                              float4* __restrict__ out) {
    const unsigned gid  = blockIdx.x * blockDim.x + threadIdx.x;
    const unsigned warp = gid >> 5;
    const unsigned lane = gid & 31;
    const unsigned t0   = warp * TPW;

    const int is64 = g_is64;

    int myidx = 0;
    if (lane < TPW) {
        const unsigned t = t0 + lane;
        int raw = is64 ? __ldg(&xraw[2u * t])   // low word, little-endian
                       : __ldg(&xraw[t]);
        myidx = min(max(raw, 0), VOCAB - 1);    // crash-proof clamp
    }

    const float4* __restrict__ Wt4 = reinterpret_cast<const float4*>(g_Wt);

    float4 v[TPW];
#pragma unroll
    for (int j = 0; j < TPW; ++j) {
        const int idx = __shfl_sync(0xffffffffu, myidx, j);
        v[j] = __ldg(&Wt4[(size_t)idx * 32 + lane]);
    }
#pragma unroll
    for (int j = 0; j < TPW; ++j) {
        __stcs(&out[(size_t)(t0 + j) * 32 + lane], v[j]);
    }
}

// ---------------------------------------------------------------------------
// kernel_launch: metadata order x, W, b. Output fp32 [819200, 128].
// ---------------------------------------------------------------------------
extern "C" void kernel_launch(void* const* d_in, const int* in_sizes, int n_in,
                              void* d_out, int out_size) {
    const int*   xraw = (const int*)d_in[0];
    const float* W    = (const float*)d_in[1];
    const float* b    = (const float*)d_in[2];
    float4*      out  = (float4*)d_out;

    detect_kernel<<<1, 32>>>(xraw);

    dim3 tb_block(32, 8);
    dim3 tb_grid(VOCAB / 32, EMBED / 32);   // (3125, 4)
    transpose_bias_kernel<<<tb_grid, tb_block>>>(W, b);

    // NTOK/TPW = 102400 warps; 8 warps per 256-thread block -> 12800 blocks.
    const unsigned warps = NTOK / TPW;
    const unsigned block = 256;
    const unsigned grid  = (warps * 32u) / block;
    gather_kernel<<<grid, block>>>(xraw, out);
}